// round 8
// baseline (speedup 1.0000x reference)
#include <cuda_runtime.h>
#include <cstdint>
#include <math.h>

// SpatialGlimpse fused, one-shot blocks, separable stencil.
// R8: block-uniform shift classes (paired outputs for K=2, direct 1-phase K=1,
// warp-uniform j mapping), geometry computed once per block. Tiling = R6/R7.

static constexpr int BATCH  = 64;
static constexpr int H = 512, W = 512, C = 3;
static constexpr int OUTHW  = 64;
static constexpr int NDEPTH = 3;
static constexpr int ROWFL  = W * C;   // 1536 floats per image row
static constexpr int NT     = 256;

// K=4: TILE_I=2, JW=32, RF=396 | K=2: TILE_I=4, JW=64, RF=396 | K=1: TILE_I=8, JW=64, RF=204
// IR = TILE_I*K + 1 = 9 for all depths.

static constexpr int NBLK4 = BATCH * 32 * 2;   // 4096  (32 row-tiles x 2 col-tiles)
static constexpr int NBLK2 = BATCH * 16;       // 1024
static constexpr int NBLK1 = BATCH * 8;        // 512
static constexpr int NBLK  = NBLK4 + NBLK2 + NBLK1;   // 5632

// SMEM floats: [0,4) mbar | [4,12) params | [12,+3564) tile | hs: hsE 288 f4, pad 4 f4, hsO 288 f4
static constexpr int TILE_OFF  = 12;
static constexpr int TILEF_MAX = 9 * 396;                  // 3564
static constexpr int HS_OFF    = TILE_OFF + TILEF_MAX;     // 3576 floats (16B aligned)
static constexpr int HSO_IDX   = 9 * 32 + 4;               // f4 offset of odd array (word delta 1168 ≡ 16 mod 32)
static constexpr int SMEM_FLOATS = HS_OFF + (9 * 32 + 4 + 9 * 32) * 4;   // 5896
static constexpr int SMEM_BYTES  = SMEM_FLOATS * 4;        // 23584

__device__ __forceinline__ uint32_t smem_u32(const void* p) {
    return (uint32_t)__cvta_generic_to_shared(p);
}
__device__ __forceinline__ void mbar_init(uint32_t a, uint32_t cnt) {
    asm volatile("mbarrier.init.shared.b64 [%0], %1;" :: "r"(a), "r"(cnt) : "memory");
}
__device__ __forceinline__ void mbar_expect_tx(uint32_t a, uint32_t bytes) {
    asm volatile("mbarrier.arrive.expect_tx.shared.b64 _, [%0], %1;" :: "r"(a), "r"(bytes) : "memory");
}
__device__ __forceinline__ void mbar_wait(uint32_t a, uint32_t parity) {
    asm volatile(
        "{\n\t"
        ".reg .pred P;\n\t"
        "LAB_WAIT_%=:\n\t"
        "mbarrier.try_wait.parity.acquire.cta.shared::cta.b64 P, [%0], %1, 0x989680;\n\t"
        "@P bra LAB_DONE_%=;\n\t"
        "bra LAB_WAIT_%=;\n\t"
        "LAB_DONE_%=:\n\t"
        "}"
        :: "r"(a), "r"(parity) : "memory");
}
__device__ __forceinline__ void bulk_g2s(uint32_t dst, const void* src, uint32_t bytes, uint32_t mbar) {
    asm volatile(
        "cp.async.bulk.shared::cluster.global.mbarrier::complete_tx::bytes [%0], [%1], %2, [%3];"
        :: "r"(dst), "l"(src), "r"(bytes), "r"(mbar) : "memory");
}

// Stage IR=9 rows into tile; publish {wy,wx,off0,validf,ytop} in smem params.
// On return (after final sync) tile data is valid for all threads.
template<int K, int TILE_I, int JW, int RF>
__device__ __forceinline__ void stage(
    const float* __restrict__ img, const float* __restrict__ offs,
    float* smem, int b, int i0, int j0)
{
    constexpr int IR   = TILE_I * K + 1;
    constexpr int SPAN = JW * K + 1;
    const int tid = threadIdx.x;
    float* tile = smem + TILE_OFF;
    int*   ip   = (int*)smem;
    const uint32_t mbar = smem_u32(smem);

    if (tid == 0) {
        const float cy = (offs[2*b + 0] + 1.0f) * (H * 0.5f);
        const float cx = (offs[2*b + 1] + 1.0f) * (W * 0.5f);
        const float Ey = cy - (OUTHW * K - 1) * 0.5f;
        const float Ex = cx - (OUTHW * K - 1) * 0.5f;
        const int   y0 = (int)floorf(Ey);
        const int   x0 = (int)floorf(Ex);
        const int px0     = x0 + j0 * K;
        const int x_hi    = min(px0 + SPAN, W);
        const int start_f = (px0 * 3) & ~3;
        const int end_f   = min((x_hi * 3 + 3) & ~3, ROWFL);
        const int validf  = end_f - start_f;
        const int ytop    = y0 + i0 * K;
        const int nvalid  = min(H - ytop, IR) - max(0, -ytop);

        smem[4] = Ey - (float)y0;      // wy
        smem[5] = Ex - (float)x0;      // wx
        ip[6] = px0 * 3 - start_f;     // off0 (0..3)
        ip[7] = validf;
        ip[8] = ytop;

        mbar_init(mbar, 1);
        asm volatile("fence.proxy.async.shared::cta;" ::: "memory");
        mbar_expect_tx(mbar, (uint32_t)(nvalid * validf * 4));
#pragma unroll
        for (int r = 0; r < IR; r++) {
            const int gy = ytop + r;
            if ((unsigned)gy < (unsigned)H) {
                const float* src = img + ((size_t)b * H + gy) * ROWFL + start_f;
                bulk_g2s(smem_u32(tile + r * RF), src, (uint32_t)(validf * 4), mbar);
            }
        }
    }
    __syncthreads();                       // params + mbar published

    const int validf = ip[7];
    const int ytop   = ip[8];
#pragma unroll
    for (int r = 0; r < IR; r++) {
        for (int f = validf + tid; f < RF; f += NT) tile[r * RF + f] = 0.0f;   // tails
        if ((unsigned)(ytop + r) >= (unsigned)H) {
            for (int f = tid; f < validf; f += NT) tile[r * RF + f] = 0.0f;    // OOB rows
        }
    }
    if (tid < 32) mbar_wait(mbar, 0);      // single-warp wait
    __syncthreads();
}

// ── K=4: Phase A JP=1 (5 f4 window, shift block-uniform) ───────────────────
template<int SH>
__device__ __forceinline__ void hred4(const float* __restrict__ rowp, float wx, float4& h)
{
    const float4* rp = reinterpret_cast<const float4*>(rowp);
    float v[20];
#pragma unroll
    for (int t = 0; t < 5; t++) {
        float4 q = rp[t];
        v[4*t+0]=q.x; v[4*t+1]=q.y; v[4*t+2]=q.z; v[4*t+3]=q.w;
    }
    const float hx0 = 1.0f - wx;
    h.x = hx0*v[SH+0] + v[SH+3]  + v[SH+6]  + v[SH+9]  + wx*v[SH+12];
    h.y = hx0*v[SH+1] + v[SH+4]  + v[SH+7]  + v[SH+10] + wx*v[SH+13];
    h.z = hx0*v[SH+2] + v[SH+5]  + v[SH+8]  + v[SH+11] + wx*v[SH+14];
    h.w = 0.0f;
}

__device__ __forceinline__ void body_k4(
    const float* __restrict__ img, const float* __restrict__ offs,
    float* __restrict__ out, float* smem, int b, int i0, int j0)
{
    constexpr int K=4, TILE_I=2, JW=32, RF=396;
    stage<K, TILE_I, JW, RF>(img, offs, smem, b, i0, j0);

    const int tid = threadIdx.x;
    float* tile = smem + TILE_OFF;
    float4* hsE = reinterpret_cast<float4*>(smem + HS_OFF);
    const float wy = smem[4], wx = smem[5];
    const int off0 = ((int*)smem)[6];
    const int base = off0 & ~3;
    const int sh   = off0 & 3;     // block-uniform

    for (int idx = tid; idx < 9 * 32; idx += NT) {
        const int r = idx >> 5, j = idx & 31;
        const float* rowp = tile + r * RF + base + 12 * j;
        float4 h;
        switch (sh) {
        case 0:  hred4<0>(rowp, wx, h); break;
        case 1:  hred4<1>(rowp, wx, h); break;
        case 2:  hred4<2>(rowp, wx, h); break;
        default: hred4<3>(rowp, wx, h); break;
        }
        hsE[r * 32 + j] = h;
    }
    __syncthreads();

    if (tid < TILE_I * JW) {
        const int ti = tid >> 5, j = tid & 31;
        const float wy0 = 1.0f - wy;
        float4 a = hsE[(ti*4+0)*32 + j];
        float o0 = wy0*a.x, o1 = wy0*a.y, o2 = wy0*a.z;
#pragma unroll
        for (int p = 1; p < 4; p++) {
            float4 m = hsE[(ti*4+p)*32 + j];
            o0 += m.x; o1 += m.y; o2 += m.z;
        }
        float4 e = hsE[(ti*4+4)*32 + j];
        o0 += wy*e.x; o1 += wy*e.y; o2 += wy*e.z;
        const size_t ob = (((size_t)b*OUTHW + (i0+ti))*OUTHW + (j0+j)) * (C*NDEPTH);
        out[ob + 0*NDEPTH + 2] = o0 * 0.0625f;
        out[ob + 1*NDEPTH + 2] = o1 * 0.0625f;
        out[ob + 2*NDEPTH + 2] = o2 * 0.0625f;
    }
}

// ── K=2: Phase A JP=2 (one 20-float window -> 2 outputs, shift block-uniform) ─
template<int SH>
__device__ __forceinline__ void hred2pair(const float* __restrict__ rowp, float wx,
                                          float4& h0, float4& h1)
{
    const float4* rp = reinterpret_cast<const float4*>(rowp);
    float v[20];
#pragma unroll
    for (int t = 0; t < 5; t++) {
        float4 q = rp[t];
        v[4*t+0]=q.x; v[4*t+1]=q.y; v[4*t+2]=q.z; v[4*t+3]=q.w;
    }
    const float hx0 = 1.0f - wx;
    h0.x = hx0*v[SH+0] + v[SH+3] + wx*v[SH+6];
    h0.y = hx0*v[SH+1] + v[SH+4] + wx*v[SH+7];
    h0.z = hx0*v[SH+2] + v[SH+5] + wx*v[SH+8];
    h0.w = 0.0f;
    h1.x = hx0*v[SH+6] + v[SH+9]  + wx*v[SH+12];
    h1.y = hx0*v[SH+7] + v[SH+10] + wx*v[SH+13];
    h1.z = hx0*v[SH+8] + v[SH+11] + wx*v[SH+14];
    h1.w = 0.0f;
}

__device__ __forceinline__ void body_k2(
    const float* __restrict__ img, const float* __restrict__ offs,
    float* __restrict__ out, float* smem, int b, int i0)
{
    constexpr int K=2, TILE_I=4, JW=64, RF=396;
    stage<K, TILE_I, JW, RF>(img, offs, smem, b, i0, 0);

    const int tid = threadIdx.x;
    float* tile = smem + TILE_OFF;
    float4* hsE = reinterpret_cast<float4*>(smem + HS_OFF);
    float4* hsO = hsE + HSO_IDX;
    const float wy = smem[4], wx = smem[5];
    const int off0 = ((int*)smem)[6];
    const int base = off0 & ~3;
    const int sh   = off0 & 3;     // block-uniform (12g keeps mod-4 fixed)

    for (int idx = tid; idx < 9 * 32; idx += NT) {
        const int r = idx >> 5, g = idx & 31;
        const float* rowp = tile + r * RF + base + 12 * g;
        float4 h0, h1;
        switch (sh) {
        case 0:  hred2pair<0>(rowp, wx, h0, h1); break;
        case 1:  hred2pair<1>(rowp, wx, h0, h1); break;
        case 2:  hred2pair<2>(rowp, wx, h0, h1); break;
        default: hred2pair<3>(rowp, wx, h0, h1); break;
        }
        hsE[r * 32 + g] = h0;      // j = 2g
        hsO[r * 32 + g] = h1;      // j = 2g+1
    }
    __syncthreads();

    {
        const int ti = tid >> 6, j = tid & 63;   // 256 outputs exactly
        const int g = j >> 1;
        const float4* arr = (j & 1) ? hsO : hsE;
        const float wy0 = 1.0f - wy;
        float4 a = arr[(ti*2+0)*32 + g];
        float4 m = arr[(ti*2+1)*32 + g];
        float4 e = arr[(ti*2+2)*32 + g];
        const float o0 = wy0*a.x + m.x + wy*e.x;
        const float o1 = wy0*a.y + m.y + wy*e.y;
        const float o2 = wy0*a.z + m.z + wy*e.z;
        const size_t ob = (((size_t)b*OUTHW + (i0+ti))*OUTHW + j) * (C*NDEPTH);
        out[ob + 0*NDEPTH + 1] = o0 * 0.25f;
        out[ob + 1*NDEPTH + 1] = o1 * 0.25f;
        out[ob + 2*NDEPTH + 1] = o2 * 0.25f;
    }
}

// ── K=1: direct single-phase bilinear (no hs, no Phase B), warp-uniform shift ─
template<int SH>
__device__ __forceinline__ void bil1(const float* __restrict__ r0p, const float* __restrict__ r1p,
                                     float wx, float wy, float& o0, float& o1, float& o2)
{
    const float hx0 = 1.0f - wx, hy0 = 1.0f - wy;
    const float4* rp0 = reinterpret_cast<const float4*>(r0p);
    float u[12];
#pragma unroll
    for (int t = 0; t < 3; t++) {
        float4 q = rp0[t];
        u[4*t+0]=q.x; u[4*t+1]=q.y; u[4*t+2]=q.z; u[4*t+3]=q.w;
    }
    const float h00 = hx0*u[SH+0] + wx*u[SH+3];
    const float h01 = hx0*u[SH+1] + wx*u[SH+4];
    const float h02 = hx0*u[SH+2] + wx*u[SH+5];
    const float4* rp1 = reinterpret_cast<const float4*>(r1p);
#pragma unroll
    for (int t = 0; t < 3; t++) {
        float4 q = rp1[t];
        u[4*t+0]=q.x; u[4*t+1]=q.y; u[4*t+2]=q.z; u[4*t+3]=q.w;
    }
    const float h10 = hx0*u[SH+0] + wx*u[SH+3];
    const float h11 = hx0*u[SH+1] + wx*u[SH+4];
    const float h12 = hx0*u[SH+2] + wx*u[SH+5];
    o0 = hy0*h00 + wy*h10;
    o1 = hy0*h01 + wy*h11;
    o2 = hy0*h02 + wy*h12;
}

__device__ __forceinline__ void body_k1(
    const float* __restrict__ img, const float* __restrict__ offs,
    float* __restrict__ out, float* smem, int b, int i0)
{
    constexpr int K=1, TILE_I=8, JW=64, RF=204;
    stage<K, TILE_I, JW, RF>(img, offs, smem, b, i0, 0);

    const int tid = threadIdx.x;
    float* tile = smem + TILE_OFF;
    const float wy = smem[4], wx = smem[5];
    const int off0 = ((int*)smem)[6];

    // j = 4*(lane&15) + (warp&3) -> (off0 + 3j) mod 4 is warp-uniform.
    const int w = tid >> 5, l = tid & 31;
    const int j  = 4 * (l & 15) + (w & 3);
    const int tb = (l >> 4) + ((w >> 2) << 1);           // 0..3
    const int sidx = off0 + 3 * j;
    const int a0   = sidx & ~3;
    const int sh   = sidx & 3;                            // warp-uniform

#pragma unroll
    for (int s = 0; s < 2; s++) {
        const int ti = tb + 4 * s;                        // 0..7
        const float* r0p = tile + ti * RF + a0;
        const float* r1p = r0p + RF;
        float o0, o1, o2;
        switch (sh) {
        case 0:  bil1<0>(r0p, r1p, wx, wy, o0, o1, o2); break;
        case 1:  bil1<1>(r0p, r1p, wx, wy, o0, o1, o2); break;
        case 2:  bil1<2>(r0p, r1p, wx, wy, o0, o1, o2); break;
        default: bil1<3>(r0p, r1p, wx, wy, o0, o1, o2); break;
        }
        const size_t ob = (((size_t)b*OUTHW + (i0+ti))*OUTHW + j) * (C*NDEPTH);
        out[ob + 0*NDEPTH + 0] = o0;
        out[ob + 1*NDEPTH + 0] = o1;
        out[ob + 2*NDEPTH + 0] = o2;
    }
}

__global__ __launch_bounds__(NT)
void glimpse_fused(const float* __restrict__ img, const float* __restrict__ offs,
                   float* __restrict__ out)
{
    extern __shared__ float smem[];
    const int bid = blockIdx.x;
    if (bid < NBLK4) {                       // K=4: 64 blocks/image (32 row x 2 col)
        const int b = bid >> 6;
        const int t = bid & 63;
        body_k4(img, offs, out, smem, b, (t >> 1) * 2, (t & 1) * 32);
    } else if (bid < NBLK4 + NBLK2) {        // K=2: 16 blocks/image
        const int r = bid - NBLK4;
        body_k2(img, offs, out, smem, r >> 4, (r & 15) * 4);
    } else {                                 // K=1: 8 blocks/image
        const int r = bid - (NBLK4 + NBLK2);
        body_k1(img, offs, out, smem, r >> 3, (r & 7) * 8);
    }
}

extern "C" void kernel_launch(void* const* d_in, const int* in_sizes, int n_in,
                              void* d_out, int out_size)
{
    (void)in_sizes; (void)n_in; (void)out_size;
    const float* img  = (const float*)d_in[0];
    const float* offs = (const float*)d_in[1];
    float* out = (float*)d_out;

    cudaFuncSetAttribute(glimpse_fused, cudaFuncAttributeMaxDynamicSharedMemorySize, SMEM_BYTES);
    glimpse_fused<<<NBLK, NT, SMEM_BYTES>>>(img, offs, out);
}

// round 9
// speedup vs baseline: 1.4307x; 1.4307x over previous
#include <cuda_runtime.h>
#include <cstdint>
#include <math.h>

// SpatialGlimpse fused, one-shot blocks, two-phase separable stencil.
// R9 = R3 structure (3584 blocks, full-width tiles, 6 CTAs/SM) + pipelined
// row-group staging: 3 mbarriers x 3 rows, Phase A consumes groups as they land.

static constexpr int BATCH  = 64;
static constexpr int H = 512, W = 512, C = 3;
static constexpr int OUTHW  = 64;
static constexpr int NDEPTH = 3;
static constexpr int ROWFL  = W * C;   // 1536 floats per image row
static constexpr int NT     = 256;

template<int K> struct Cfg;
template<> struct Cfg<1> { static constexpr int TILE_I = 8; static constexpr int ROWF = 204; static constexpr int NV = 3; };
template<> struct Cfg<2> { static constexpr int TILE_I = 4; static constexpr int ROWF = 396; static constexpr int NV = 3; };
template<> struct Cfg<4> { static constexpr int TILE_I = 2; static constexpr int ROWF = 780; static constexpr int NV = 5; };
// IR = TILE_I*K + 1 = 9 input rows for every depth; 3 groups of 3 rows.

static constexpr int NBLK4 = BATCH * (OUTHW / Cfg<4>::TILE_I);   // 2048
static constexpr int NBLK2 = BATCH * (OUTHW / Cfg<2>::TILE_I);   // 1024
static constexpr int NBLK1 = BATCH * (OUTHW / Cfg<1>::TILE_I);   // 512
static constexpr int NBLK  = NBLK4 + NBLK2 + NBLK1;              // 3584

// SMEM floats: [0,8) three mbarriers (8B each at float idx 0,2,4; idx 6,7 pad)
// | tile 9*ROWF | hs 9*64 float4. Max = K4: (8 + 7020 + 2304)*4 = 37328 B.
static constexpr int TILE_OFF   = 8;
static constexpr int SMEM_BYTES = (TILE_OFF + 9 * Cfg<4>::ROWF + 9 * OUTHW * 4) * 4;

__device__ __forceinline__ uint32_t smem_u32(const void* p) {
    return (uint32_t)__cvta_generic_to_shared(p);
}
__device__ __forceinline__ void mbar_init(uint32_t a, uint32_t cnt) {
    asm volatile("mbarrier.init.shared.b64 [%0], %1;" :: "r"(a), "r"(cnt) : "memory");
}
__device__ __forceinline__ void mbar_expect_tx(uint32_t a, uint32_t bytes) {
    asm volatile("mbarrier.arrive.expect_tx.shared.b64 _, [%0], %1;" :: "r"(a), "r"(bytes) : "memory");
}
__device__ __forceinline__ void mbar_wait(uint32_t a, uint32_t parity) {
    asm volatile(
        "{\n\t"
        ".reg .pred P;\n\t"
        "LAB_WAIT_%=:\n\t"
        "mbarrier.try_wait.parity.acquire.cta.shared::cta.b64 P, [%0], %1, 0x989680;\n\t"
        "@P bra LAB_DONE_%=;\n\t"
        "bra LAB_WAIT_%=;\n\t"
        "LAB_DONE_%=:\n\t"
        "}"
        :: "r"(a), "r"(parity) : "memory");
}
__device__ __forceinline__ void bulk_g2s(uint32_t dst, const void* src, uint32_t bytes, uint32_t mbar) {
    asm volatile(
        "cp.async.bulk.shared::cluster.global.mbarrier::complete_tx::bytes [%0], [%1], %2, [%3];"
        :: "r"(dst), "l"(src), "r"(bytes), "r"(mbar) : "memory");
}

// Horizontal weighted sum for one (row, j): window of K+1 pixels x 3 channels.
// SH = sub-float4 shift (compile-time so v[] stays in registers).
template<int K, int SH>
__device__ __forceinline__ void hreduce_one(const float* __restrict__ rowp, float wx, float4& h)
{
    constexpr int NV = Cfg<K>::NV;
    const float hx0 = 1.0f - wx;
    float v[4 * NV];
    const float4* rp = reinterpret_cast<const float4*>(rowp);
#pragma unroll
    for (int t = 0; t < NV; t++) {
        float4 q = rp[t];
        v[4*t+0] = q.x; v[4*t+1] = q.y; v[4*t+2] = q.z; v[4*t+3] = q.w;
    }
    float r0 = hx0 * v[SH + 0] + wx * v[SH + 3*K + 0];
    float r1 = hx0 * v[SH + 1] + wx * v[SH + 3*K + 1];
    float r2 = hx0 * v[SH + 2] + wx * v[SH + 3*K + 2];
#pragma unroll
    for (int q = 1; q < K; q++) {
        r0 += v[SH + 3*q + 0];
        r1 += v[SH + 3*q + 1];
        r2 += v[SH + 3*q + 2];
    }
    h.x = r0; h.y = r1; h.z = r2; h.w = 0.0f;
}

template<int K, int D>
__device__ __forceinline__ void glimpse_body(
    const float* __restrict__ img, const float* __restrict__ offs,
    float* __restrict__ out, float* smem, int b, int i0)
{
    constexpr int TILE_I = Cfg<K>::TILE_I;
    constexpr int RF     = Cfg<K>::ROWF;
    constexpr int IR     = TILE_I * K + 1;      // 9
    constexpr int SPAN   = OUTHW * K + 1;

    float* tile = smem + TILE_OFF;
    float4* hs  = reinterpret_cast<float4*>(smem + TILE_OFF + IR * RF);
    const int tid = threadIdx.x;

    // All threads compute geometry in parallel (R3/R7 style — no publish sync).
    const float cy = (offs[2*b + 0] + 1.0f) * (H * 0.5f);
    const float cx = (offs[2*b + 1] + 1.0f) * (W * 0.5f);
    const float Ey = cy - (OUTHW * K - 1) * 0.5f;
    const float Ex = cx - (OUTHW * K - 1) * 0.5f;
    const int   y0 = (int)floorf(Ey);
    const int   x0 = (int)floorf(Ex);
    const float wy = Ey - (float)y0;
    const float wx = Ex - (float)x0;

    const int x_hi    = min(x0 + SPAN, W);
    const int start_f = (x0 * 3) & ~3;
    const int end_f   = min((x_hi * 3 + 3) & ~3, ROWFL);
    const int validf  = end_f - start_f;
    const int off0    = x0 * 3 - start_f;       // 0..3
    const int rowbytes = validf * 4;            // multiple of 16
    const int ytop    = y0 + i0 * K;

    // tid0: init 3 mbars, set per-group expectations, fire all copies immediately.
    if (tid == 0) {
#pragma unroll
        for (int g = 0; g < 3; g++) mbar_init(smem_u32(smem + 2 * g), 1);
        asm volatile("fence.proxy.async.shared::cta;" ::: "memory");
#pragma unroll
        for (int g = 0; g < 3; g++) {
            int nv = 0;
#pragma unroll
            for (int r = 3 * g; r < 3 * g + 3; r++)
                if ((unsigned)(ytop + r) < (unsigned)H) nv++;
            mbar_expect_tx(smem_u32(smem + 2 * g), (uint32_t)(nv * rowbytes));
        }
#pragma unroll
        for (int r = 0; r < IR; r++) {
            const int gy = ytop + r;
            if ((unsigned)gy < (unsigned)H) {
                const float* src = img + ((size_t)b * H + gy) * ROWFL + start_f;
                bulk_g2s(smem_u32(tile + r * RF), src, (uint32_t)rowbytes, smem_u32(smem + 2 * (r / 3)));
            }
        }
    }

    // Meanwhile: zero tails (disjoint from bulk-copy dest bytes) and OOB rows.
    {
        const int ntail = RF - validf;          // >= 3 always
        for (int idx = tid; idx < IR * ntail; idx += NT) {
            const int r = idx / ntail;
            tile[r * RF + validf + idx % ntail] = 0.0f;
        }
#pragma unroll
        for (int r = 0; r < IR; r++) {
            if ((unsigned)(ytop + r) >= (unsigned)H) {
                for (int f = tid; f < validf; f += NT) tile[r * RF + f] = 0.0f;
            }
        }
    }
    __syncthreads();   // zeros done + mbar inits visible to all

    // ── Phase A, pipelined per row-group: consume 3 rows as soon as they land.
    //    192 windows per group; threads 192..255 just pass through the wait. ──
    const int j    = tid % OUTHW;               // for tid < 192
    const int rsub = tid / OUTHW;               // 0..2
    const int sidx = off0 + 3 * K * j;
    const int a0   = sidx & ~3;
    const int sh   = sidx & 3;
#pragma unroll
    for (int g = 0; g < 3; g++) {
        mbar_wait(smem_u32(smem + 2 * g), 0);
        if (tid < 3 * OUTHW) {
            const int r = 3 * g + rsub;
            const float* rowp = tile + r * RF + a0;
            float4 h;
            switch (sh) {
            case 0:  hreduce_one<K,0>(rowp, wx, h); break;
            case 1:  hreduce_one<K,1>(rowp, wx, h); break;
            case 2:  hreduce_one<K,2>(rowp, wx, h); break;
            default: hreduce_one<K,3>(rowp, wx, h); break;
            }
            hs[r * OUTHW + j] = h;
        }
    }
    __syncthreads();

    // ── Phase B: vertical reduction over hs. Conflict-free. ──
    constexpr float inv = 1.0f / (K * K);
    const float wy0 = 1.0f - wy;
    for (int o = tid; o < TILE_I * OUTHW; o += NT) {
        const int ti = o >> 6;
        const int jj = o & 63;
        float4 a = hs[(ti * K) * OUTHW + jj];
        float o0 = wy0 * a.x, o1 = wy0 * a.y, o2 = wy0 * a.z;
#pragma unroll
        for (int p = 1; p < K; p++) {
            float4 m = hs[(ti * K + p) * OUTHW + jj];
            o0 += m.x; o1 += m.y; o2 += m.z;
        }
        float4 e = hs[(ti * K + K) * OUTHW + jj];
        o0 += wy * e.x; o1 += wy * e.y; o2 += wy * e.z;

        const size_t ob = (((size_t)b * OUTHW + (i0 + ti)) * OUTHW + jj) * (C * NDEPTH);
        out[ob + 0 * NDEPTH + D] = o0 * inv;
        out[ob + 1 * NDEPTH + D] = o1 * inv;
        out[ob + 2 * NDEPTH + D] = o2 * inv;
    }
}

__global__ __launch_bounds__(NT)
void glimpse_fused(const float* __restrict__ img, const float* __restrict__ offs,
                   float* __restrict__ out)
{
    extern __shared__ float smem[];
    const int bid = blockIdx.x;
    if (bid < NBLK4) {                                   // K=4: 32 blocks/image
        glimpse_body<4, 2>(img, offs, out, smem, bid >> 5, (bid & 31) * Cfg<4>::TILE_I);
    } else if (bid < NBLK4 + NBLK2) {                    // K=2: 16 blocks/image
        const int r = bid - NBLK4;
        glimpse_body<2, 1>(img, offs, out, smem, r >> 4, (r & 15) * Cfg<2>::TILE_I);
    } else {                                             // K=1: 8 blocks/image
        const int r = bid - (NBLK4 + NBLK2);
        glimpse_body<1, 0>(img, offs, out, smem, r >> 3, (r & 7) * Cfg<1>::TILE_I);
    }
}

extern "C" void kernel_launch(void* const* d_in, const int* in_sizes, int n_in,
                              void* d_out, int out_size)
{
    (void)in_sizes; (void)n_in; (void)out_size;
    const float* img  = (const float*)d_in[0];
    const float* offs = (const float*)d_in[1];
    float* out = (float*)d_out;

    cudaFuncSetAttribute(glimpse_fused, cudaFuncAttributeMaxDynamicSharedMemorySize, SMEM_BYTES);
    glimpse_fused<<<NBLK, NT, SMEM_BYTES>>>(img, offs, out);
}